// round 15
// baseline (speedup 1.0000x reference)
#include <cuda_runtime.h>
#include <cstdint>

#define Nn 100000
#define Ee 1600000
#define Hd 128
#define Bb 4
#define AST 132
#define WST 136
#define SMEMX ((64 * AST + 128 * WST) * 4)
#define PGRID 296

__device__ __align__(256) int   g_cnt[Nn];
__device__ __align__(256) int   g_rowptr[Nn + 1];
__device__ __align__(256) int   g_wptr[Nn];
__device__ __align__(256) int   g_src[Ee];
__device__ __align__(256) float g_eas[Ee];
__device__ __align__(256) float g_inv[Nn];
__device__ __align__(256) float g_h[(size_t)Nn * Hd];
__device__ __align__(256) float g_A0[(size_t)Nn * Hd];
__device__ __align__(256) float g_B0[(size_t)Nn * Hd];
__device__ __align__(256) float g_A1[(size_t)Nn * Hd];
__device__ __align__(256) float g_B1[(size_t)Nn * Hd];
__device__ __align__(256) float g_hid[(size_t)Nn * Hd];
__device__ __align__(256) float g_tf[Bb * Hd];
__device__ __align__(256) float g_cf[Bb * Hd];

__device__ __forceinline__ uint32_t tf32r(float x) {
    uint32_t r;
    asm("cvt.rna.tf32.f32 %0, %1;" : "=r"(r) : "f"(x));
    return r;
}
__device__ __forceinline__ void mma8(float* d, const uint32_t* a, uint32_t b0, uint32_t b1) {
    asm("mma.sync.aligned.m16n8k8.row.col.f32.tf32.tf32.f32 "
        "{%0,%1,%2,%3}, {%4,%5,%6,%7}, {%8,%9}, {%0,%1,%2,%3};"
        : "+f"(d[0]), "+f"(d[1]), "+f"(d[2]), "+f"(d[3])
        : "r"(a[0]), "r"(a[1]), "r"(a[2]), "r"(a[3]), "r"(b0), "r"(b1));
}

__device__ __forceinline__ void load_A(const float* __restrict__ in, float* As,
                                       int r0, int M, int t) {
    for (int idx = t; idx < 2048; idx += 256) {
        int row = idx >> 5, k4 = (idx & 31) * 4;
        float4 v = make_float4(0.f, 0.f, 0.f, 0.f);
        int gr = r0 + row;
        if (gr < M) v = *(const float4*)&in[(size_t)gr * 128 + k4];
        uint4 u; u.x = tf32r(v.x); u.y = tf32r(v.y); u.z = tf32r(v.z); u.w = tf32r(v.w);
        *(uint4*)&As[row * AST + k4] = u;
    }
}
__device__ __forceinline__ void load_W(const float* __restrict__ W, float* Ws, int t) {
    for (int idx = t; idx < 4096; idx += 256) {
        int k = idx >> 5, n4 = (idx & 31) * 4;
        float4 w = ((const float4*)W)[idx];
        uint4 u; u.x = tf32r(w.x); u.y = tf32r(w.y); u.z = tf32r(w.z); u.w = tf32r(w.w);
        *(uint4*)&Ws[k * WST + n4] = u;
    }
}

// gather into smem A-tile: row rl of tile = node r0+rl; warp w owns rows [8w,8w+8)
__device__ __forceinline__ void gather_load(const float* __restrict__ Ain,
                                            const float* __restrict__ Bin,
                                            float4 wc, float* As, int r0, int M, int t) {
    int warp = t >> 5, lane = t & 31;
#pragma unroll
    for (int i = 0; i < 8; i++) {
        int rl = warp * 8 + i;
        int n = r0 + rl;
        float4 acc = make_float4(0.f, 0.f, 0.f, 0.f);
        if (n < M) {
            float4 a = *(const float4*)&Ain[(size_t)n * 128 + lane * 4];
            int e = g_rowptr[n], e1 = g_rowptr[n + 1];
            for (; e + 2 <= e1; e += 2) {
                int s0 = g_src[e], s1 = g_src[e + 1];
                float ea0 = g_eas[e], ea1 = g_eas[e + 1];
                float4 b0 = *(const float4*)&Bin[(size_t)s0 * 128 + lane * 4];
                float4 b1 = *(const float4*)&Bin[(size_t)s1 * 128 + lane * 4];
                acc.x += fmaxf(a.x + b0.x + ea0 * wc.x, 0.f) + fmaxf(a.x + b1.x + ea1 * wc.x, 0.f);
                acc.y += fmaxf(a.y + b0.y + ea0 * wc.y, 0.f) + fmaxf(a.y + b1.y + ea1 * wc.y, 0.f);
                acc.z += fmaxf(a.z + b0.z + ea0 * wc.z, 0.f) + fmaxf(a.z + b1.z + ea1 * wc.z, 0.f);
                acc.w += fmaxf(a.w + b0.w + ea0 * wc.w, 0.f) + fmaxf(a.w + b1.w + ea1 * wc.w, 0.f);
            }
            if (e < e1) {
                int s0 = g_src[e];
                float ea0 = g_eas[e];
                float4 b0 = *(const float4*)&Bin[(size_t)s0 * 128 + lane * 4];
                acc.x += fmaxf(a.x + b0.x + ea0 * wc.x, 0.f);
                acc.y += fmaxf(a.y + b0.y + ea0 * wc.y, 0.f);
                acc.z += fmaxf(a.z + b0.z + ea0 * wc.z, 0.f);
                acc.w += fmaxf(a.w + b0.w + ea0 * wc.w, 0.f);
            }
            float iv = g_inv[n];
            acc.x *= iv; acc.y *= iv; acc.z *= iv; acc.w *= iv;
        }
        uint4 u; u.x = tf32r(acc.x); u.y = tf32r(acc.y); u.z = tf32r(acc.z); u.w = tf32r(acc.w);
        *(uint4*)&As[rl * AST + lane * 4] = u;
    }
}

__device__ __forceinline__ void warp_mma(const float* As, const float* Ws,
                                         int wm, int wn, int g, int tg,
                                         float (&acc)[2][4][4]) {
#pragma unroll
    for (int mi = 0; mi < 2; mi++)
#pragma unroll
        for (int ni = 0; ni < 4; ni++)
#pragma unroll
            for (int c = 0; c < 4; c++) acc[mi][ni][c] = 0.f;
    const uint32_t* Au = (const uint32_t*)As;
    const uint32_t* Wu = (const uint32_t*)Ws;
#pragma unroll 4
    for (int k0 = 0; k0 < 128; k0 += 8) {
        uint32_t a[2][4];
#pragma unroll
        for (int mi = 0; mi < 2; mi++) {
            int r = wm * 32 + mi * 16 + g;
            a[mi][0] = Au[r * AST + k0 + tg];
            a[mi][1] = Au[(r + 8) * AST + k0 + tg];
            a[mi][2] = Au[r * AST + k0 + tg + 4];
            a[mi][3] = Au[(r + 8) * AST + k0 + tg + 4];
        }
#pragma unroll
        for (int ni = 0; ni < 4; ni++) {
            int cb = wn * 32 + ni * 8 + g;
            uint32_t b0 = Wu[(k0 + tg) * WST + cb];
            uint32_t b1 = Wu[(k0 + tg + 4) * WST + cb];
            mma8(acc[0][ni], a[0], b0, b1);
            mma8(acc[1][ni], a[1], b0, b1);
        }
    }
}

// EPI: 0 = out+bias (+RELU), 1 = out raw, 2 = h-update (outp == hio)
// GATHER: phase input comes from edge gather instead of dense rows
template <int EPI, bool RELU, bool GATHER>
__device__ __forceinline__ void run_pass(const float* __restrict__ in,
                                         float* __restrict__ outp,
                                         const float* bs, float* As, const float* Ws,
                                         int M, int nt, int t,
                                         const float* Ain = nullptr,
                                         const float* Bin = nullptr,
                                         float4 wc = {0.f, 0.f, 0.f, 0.f}) {
    int wid = t >> 5, lane = t & 31;
    int g = lane >> 2, tg = lane & 3;
    int wm = wid & 1, wn = wid >> 1;
    int tile = blockIdx.x;
    if (tile < nt) {
        if (GATHER) gather_load(Ain, Bin, wc, As, tile * 64, M, t);
        else        load_A(in, As, tile * 64, M, t);
    }
    __syncthreads();
    for (; tile < nt; tile += gridDim.x) {
        float acc[2][4][4];
        warp_mma(As, Ws, wm, wn, g, tg, acc);
        __syncthreads();
        int next = tile + gridDim.x;
        if (next < nt) {
            if (GATHER) gather_load(Ain, Bin, wc, As, next * 64, M, t);
            else        load_A(in, As, next * 64, M, t);
        }
        int r0 = tile * 64;
#pragma unroll
        for (int mi = 0; mi < 2; mi++) {
            int row = r0 + wm * 32 + mi * 16 + g;
#pragma unroll
            for (int ni = 0; ni < 4; ni++) {
                int col = wn * 32 + ni * 8 + 2 * tg;
#pragma unroll
                for (int half = 0; half < 2; half++) {
                    int rr = row + half * 8;
                    if (rr >= M) continue;
                    float vx = acc[mi][ni][half * 2 + 0];
                    float vy = acc[mi][ni][half * 2 + 1];
                    if (EPI == 0) {
                        vx += bs[col]; vy += bs[col + 1];
                        if (RELU) { vx = fmaxf(vx, 0.f); vy = fmaxf(vy, 0.f); }
                        float2 v; v.x = vx; v.y = vy;
                        *(float2*)&outp[(size_t)rr * 128 + col] = v;
                    } else if (EPI == 1) {
                        float2 v; v.x = vx; v.y = vy;
                        *(float2*)&outp[(size_t)rr * 128 + col] = v;
                    } else {
                        float mask = (g_cnt[rr] > 0) ? 1.f : 0.f;
                        float2 hv = *(const float2*)&outp[(size_t)rr * 128 + col];
                        hv.x += fmaxf(vx + bs[col]     * mask, 0.f);
                        hv.y += fmaxf(vy + bs[col + 1] * mask, 0.f);
                        *(float2*)&outp[(size_t)rr * 128 + col] = hv;
                    }
                }
            }
        }
        __syncthreads();
    }
}

// ---------------- persistent single GEMM ----------------
template <bool RELU>
__global__ void __launch_bounds__(256, 2)
k_gemm_t(const float* __restrict__ in, const float* __restrict__ W,
         const float* __restrict__ bias, float* __restrict__ out, int M, int nt) {
    extern __shared__ float sm[];
    float* As = sm; float* Ws = sm + 64 * AST;
    __shared__ float bs[128];
    int t = threadIdx.x;
    load_W(W, Ws, t);
    if (t < 128) bs[t] = bias[t];
    run_pass<0, RELU, false>(in, out, bs, As, Ws, M, nt, t);
}

// ---------------- persistent A/B pair ----------------
__global__ void __launch_bounds__(256, 2)
k_gemmAB_t(const float* __restrict__ in, const float* __restrict__ W1a,
           const float* __restrict__ b1, const float* __restrict__ W1b,
           float* __restrict__ Aout, float* __restrict__ Bout, int M, int nt) {
    extern __shared__ float sm[];
    float* As = sm; float* Ws = sm + 64 * AST;
    __shared__ float bs[128];
    int t = threadIdx.x;
    load_W(W1a, Ws, t);
    if (t < 128) bs[t] = b1[t];
    run_pass<0, false, false>(in, Aout, bs, As, Ws, M, nt, t);
    __syncthreads();
    load_W(W1b, Ws, t);
    run_pass<1, false, false>(in, Bout, bs, As, Ws, M, nt, t);
}

// ---- fused layer: h += relu(gather@W2 + b2*mask); then A' = h@W1a+b1; B' = h@W1b ----
__global__ void __launch_bounds__(256, 2)
k_fused_t(const float* __restrict__ Ain, const float* __restrict__ Bin,
          const float* __restrict__ w1c,
          const float* __restrict__ W2, const float* __restrict__ b2,
          float* __restrict__ hio,
          const float* __restrict__ W1a, const float* __restrict__ b1,
          const float* __restrict__ W1b,
          float* __restrict__ Aout, float* __restrict__ Bout, int M, int nt, int doAB) {
    extern __shared__ float sm[];
    float* As = sm; float* Ws = sm + 64 * AST;
    __shared__ float bs0[128], bs1[128];
    int t = threadIdx.x, lane = t & 31;
    float4 wc = ((const float4*)w1c)[lane];
    load_W(W2, Ws, t);
    if (t < 128) bs0[t] = b2[t];
    if (t >= 128) bs1[t - 128] = b1[t - 128];
    run_pass<2, false, true>(nullptr, hio, bs0, As, Ws, M, nt, t, Ain, Bin, wc);
    if (!doAB) return;
    __syncthreads();
    load_W(W1a, Ws, t);
    run_pass<0, false, false>(hio, Aout, bs1, As, Ws, M, nt, t);
    __syncthreads();
    load_W(W1b, Ws, t);
    run_pass<1, false, false>(hio, Bout, bs1, As, Ws, M, nt, t);
}

// ---------------- sort / small kernels ----------------
__global__ void k_zero(int N) {
    int i = blockIdx.x * blockDim.x + threadIdx.x;
    if (i < N) g_cnt[i] = 0;
}
__global__ void k_hist(const int* __restrict__ ei, int E) {
    int i = blockIdx.x * blockDim.x + threadIdx.x;
    if (i < E) atomicAdd(&g_cnt[ei[(size_t)E + i]], 1);
}
__global__ void k_scan(int n) {
    __shared__ int wsum[32];
    __shared__ int carry;
    int t = threadIdx.x, lane = t & 31, w = t >> 5;
    if (t == 0) carry = 0;
    __syncthreads();
    for (int base = 0; base < n; base += 1024) {
        int i = base + t;
        int v = (i < n) ? g_cnt[i] : 0;
        int x = v;
#pragma unroll
        for (int o = 1; o < 32; o <<= 1) { int y = __shfl_up_sync(~0u, x, o); if (lane >= o) x += y; }
        if (lane == 31) wsum[w] = x;
        __syncthreads();
        if (w == 0) {
            int s = wsum[lane];
#pragma unroll
            for (int o = 1; o < 32; o <<= 1) { int y = __shfl_up_sync(~0u, s, o); if (lane >= o) s += y; }
            wsum[lane] = s;
        }
        __syncthreads();
        int off = carry + (w ? wsum[w - 1] : 0);
        if (i < n) g_rowptr[i] = off + x - v;
        int total = wsum[31];
        __syncthreads();
        if (t == 0) carry += total;
        __syncthreads();
    }
    if (threadIdx.x == 0) g_rowptr[n] = carry;
}
__global__ void k_prep(int N) {
    int i = blockIdx.x * blockDim.x + threadIdx.x;
    if (i < N) {
        int c = g_cnt[i];
        g_inv[i] = 1.0f / (float)(c > 1 ? c : 1);
        g_wptr[i] = g_rowptr[i];
    }
}
__global__ void k_scatter(const int* __restrict__ ei, const float* __restrict__ ea, int E) {
    int i = blockIdx.x * blockDim.x + threadIdx.x;
    if (i < E) {
        int d = ei[(size_t)E + i];
        int pos = atomicAdd(&g_wptr[d], 1);
        g_src[pos] = ei[i];
        g_eas[pos] = ea[i];
    }
}
__global__ void k_input1(const float* __restrict__ x, const float* __restrict__ w1,
                         const float* __restrict__ b1, int N) {
    int idx = blockIdx.x * blockDim.x + threadIdx.x;
    if (idx >= N * 128) return;
    int n = idx >> 7, c = idx & 127;
    float v = fmaf(x[n*3], w1[c], fmaf(x[n*3+1], w1[128+c], fmaf(x[n*3+2], w1[256+c], b1[c])));
    g_hid[idx] = fmaxf(v, 0.f);
}
__global__ void k_addfeat(const int* __restrict__ batch, int N) {
    int idx = blockIdx.x * blockDim.x + threadIdx.x;
    if (idx >= N * 128) return;
    int n = idx >> 7, c = idx & 127;
    int b = batch[n];
    g_h[idx] += g_tf[b * 128 + c] + g_cf[b * 128 + c];
}
__global__ void k_small(const float* __restrict__ tv, const float* __restrict__ cond,
                        const float* __restrict__ tw1, const float* __restrict__ tb1,
                        const float* __restrict__ tw2, const float* __restrict__ tb2,
                        const float* __restrict__ cw1, const float* __restrict__ cb1,
                        const float* __restrict__ cw2, const float* __restrict__ cb2,
                        int B, int C) {
    __shared__ float ht[Bb][Hd];
    __shared__ float hc[Bb][Hd];
    int c = threadIdx.x;
    for (int i = 0; i < B; i++) {
        ht[i][c] = fmaxf(fmaf(tv[i], tw1[c], tb1[c]), 0.f);
        float s = cb1[c];
        for (int j = 0; j < C; j++) s = fmaf(cond[i * C + j], cw1[j * 128 + c], s);
        hc[i][c] = fmaxf(s, 0.f);
    }
    __syncthreads();
    for (int i = 0; i < B; i++) {
        float s1 = tb2[c], s2 = cb2[c];
        for (int k = 0; k < 128; k++) {
            s1 = fmaf(ht[i][k], tw2[k * 128 + c], s1);
            s2 = fmaf(hc[i][k], cw2[k * 128 + c], s2);
        }
        g_tf[i * 128 + c] = s1;
        g_cf[i * 128 + c] = s2;
    }
}
__global__ void k_out2(const float* __restrict__ w2, const float* __restrict__ b2,
                       float* __restrict__ out, int N) {
    int idx = blockIdx.x * blockDim.x + threadIdx.x;
    if (idx >= N * 3) return;
    int n = idx / 3, j = idx % 3;
    float s = b2[j];
    const float* hrow = &g_hid[(size_t)n * 128];
#pragma unroll 8
    for (int k = 0; k < 128; k++) s = fmaf(hrow[k], w2[k * 3 + j], s);
    out[idx] = s;
}

extern "C" void kernel_launch(void* const* d_in, const int* in_sizes, int n_in,
                              void* d_out, int out_size) {
    const float* x      = (const float*)d_in[0];
    const int*   ei     = (const int*)d_in[1];
    const float* ea     = (const float*)d_in[2];
    const float* tvec   = (const float*)d_in[3];
    const int*   batch  = (const int*)d_in[4];
    const float* cond   = (const float*)d_in[5];
    const float* in_w1  = (const float*)d_in[6];
    const float* in_b1  = (const float*)d_in[7];
    const float* in_w2  = (const float*)d_in[8];
    const float* in_b2  = (const float*)d_in[9];
    const float* t_w1   = (const float*)d_in[10];
    const float* t_b1   = (const float*)d_in[11];
    const float* t_w2   = (const float*)d_in[12];
    const float* t_b2   = (const float*)d_in[13];
    const float* c_w1   = (const float*)d_in[14];
    const float* c_b1   = (const float*)d_in[15];
    const float* c_w2   = (const float*)d_in[16];
    const float* c_b2   = (const float*)d_in[17];
    const float* convW1 = (const float*)d_in[18];
    const float* convb1 = (const float*)d_in[19];
    const float* convW2 = (const float*)d_in[20];
    const float* convb2 = (const float*)d_in[21];
    const float* out_w1 = (const float*)d_in[22];
    const float* out_b1 = (const float*)d_in[23];
    const float* out_w2 = (const float*)d_in[24];
    const float* out_b2 = (const float*)d_in[25];

    int N = in_sizes[0] / 3;
    int E = in_sizes[1] / 2;
    int B = in_sizes[3];
    int C = in_sizes[5] / (B > 0 ? B : 1);
    float* out = (float*)d_out;

    float *p_h = 0, *p_A0 = 0, *p_B0 = 0, *p_A1 = 0, *p_B1 = 0, *p_hid = 0;
    cudaGetSymbolAddress((void**)&p_h,   g_h);
    cudaGetSymbolAddress((void**)&p_A0,  g_A0);
    cudaGetSymbolAddress((void**)&p_B0,  g_B0);
    cudaGetSymbolAddress((void**)&p_A1,  g_A1);
    cudaGetSymbolAddress((void**)&p_B1,  g_B1);
    cudaGetSymbolAddress((void**)&p_hid, g_hid);

    cudaFuncSetAttribute(k_gemm_t<false>, cudaFuncAttributeMaxDynamicSharedMemorySize, SMEMX);
    cudaFuncSetAttribute(k_gemm_t<true>,  cudaFuncAttributeMaxDynamicSharedMemorySize, SMEMX);
    cudaFuncSetAttribute(k_gemmAB_t,      cudaFuncAttributeMaxDynamicSharedMemorySize, SMEMX);
    cudaFuncSetAttribute(k_fused_t,       cudaFuncAttributeMaxDynamicSharedMemorySize, SMEMX);

    int nt = (N + 63) / 64;

    k_input1<<<(N * 128 + 255) / 256, 256>>>(x, in_w1, in_b1, N);
    k_small<<<1, 128>>>(tvec, cond, t_w1, t_b1, t_w2, t_b2, c_w1, c_b1, c_w2, c_b2, B, C);
    k_zero<<<(N + 255) / 256, 256>>>(N);
    k_gemm_t<false><<<PGRID, 256, SMEMX>>>(p_hid, in_w2, in_b2, p_h, N, nt);   // ncu slot 4
    k_hist<<<(E + 255) / 256, 256>>>(ei, E);
    k_scan<<<1, 1024>>>(N);
    k_prep<<<(N + 255) / 256, 256>>>(N);
    k_scatter<<<(E + 255) / 256, 256>>>(ei, ea, E);
    k_addfeat<<<(N * 128 + 255) / 256, 256>>>(batch, N);

    // layer-0 A/B into buffer 0
    k_gemmAB_t<<<PGRID, 256, SMEMX>>>(p_h, convW1, convb1, convW1 + 128 * 128, p_A0, p_B0, N, nt);

    for (int l = 0; l < 6; l++) {
        const float* W1 = convW1 + (size_t)l * 257 * 128;
        const float* W1n = convW1 + (size_t)(l + 1) * 257 * 128;
        int doAB = (l < 5) ? 1 : 0;
        float* Ai = (l & 1) ? p_A1 : p_A0;
        float* Bi = (l & 1) ? p_B1 : p_B0;
        float* Ao = (l & 1) ? p_A0 : p_A1;
        float* Bo = (l & 1) ? p_B0 : p_B1;
        k_fused_t<<<PGRID, 256, SMEMX>>>(Ai, Bi, W1 + 256 * 128,
                                         convW2 + (size_t)l * 128 * 128, convb2 + l * 128,
                                         p_h,
                                         doAB ? W1n : convW1,
                                         doAB ? (convb1 + (l + 1) * 128) : convb1,
                                         doAB ? (W1n + 128 * 128) : convW1,
                                         Ao, Bo, N, nt, doAB);
    }

    k_gemm_t<true><<<PGRID, 256, SMEMX>>>(p_h, out_w1, out_b1, p_hid, N, nt);
    k_out2<<<(N * 3 + 255) / 256, 256>>>(out_w2, out_b2, out, N);
}

// round 16
// speedup vs baseline: 1.5915x; 1.5915x over previous
#include <cuda_runtime.h>
#include <cuda_bf16.h>
#include <cstdint>

#define Nn 100000
#define Ee 1600000
#define Hd 128
#define Bb 4
#define AST 132
#define WST 136
#define SMEMX ((64 * AST + 128 * WST) * 4)
#define PGRID 296

__device__ __align__(256) int   g_cnt[Nn];
__device__ __align__(256) int   g_rowptr[Nn + 1];
__device__ __align__(256) int   g_wptr[Nn];
__device__ __align__(256) int   g_src[Ee];
__device__ __align__(256) float g_eas[Ee];
__device__ __align__(256) float g_inv[Nn];
__device__ __align__(256) float g_h[(size_t)Nn * Hd];
__device__ __align__(256) float g_A[(size_t)Nn * Hd];
__device__ __align__(256) __nv_bfloat16 g_Bm[(size_t)Nn * Hd];
__device__ __align__(256) float g_S[(size_t)Nn * Hd];
__device__ __align__(256) float g_hid[(size_t)Nn * Hd];
__device__ __align__(256) float g_tf[Bb * Hd];
__device__ __align__(256) float g_cf[Bb * Hd];

__device__ __forceinline__ uint32_t tf32r(float x) {
    uint32_t r;
    asm("cvt.rna.tf32.f32 %0, %1;" : "=r"(r) : "f"(x));
    return r;
}
__device__ __forceinline__ void mma8(float* d, const uint32_t* a, uint32_t b0, uint32_t b1) {
    asm volatile(
        "mma.sync.aligned.m16n8k8.row.col.f32.tf32.tf32.f32 "
        "{%0,%1,%2,%3}, {%4,%5,%6,%7}, {%8,%9}, {%0,%1,%2,%3};"
        : "+f"(d[0]), "+f"(d[1]), "+f"(d[2]), "+f"(d[3])
        : "r"(a[0]), "r"(a[1]), "r"(a[2]), "r"(a[3]), "r"(b0), "r"(b1));
}

__device__ __forceinline__ float4 ldB(const __nv_bfloat16* __restrict__ Bm, int s, int lane) {
    uint2 p = *(const uint2*)(Bm + (size_t)s * 128 + lane * 4);
    __nv_bfloat162 u0 = *reinterpret_cast<__nv_bfloat162*>(&p.x);
    __nv_bfloat162 u1 = *reinterpret_cast<__nv_bfloat162*>(&p.y);
    float2 f0 = __bfloat1622float2(u0);
    float2 f1 = __bfloat1622float2(u1);
    return make_float4(f0.x, f0.y, f1.x, f1.y);
}

__device__ __forceinline__ void load_A(const float* __restrict__ in, float* As,
                                       int r0, int M, int t) {
    for (int idx = t; idx < 2048; idx += 256) {
        int row = idx >> 5, k4 = (idx & 31) * 4;
        float4 v = make_float4(0.f, 0.f, 0.f, 0.f);
        int gr = r0 + row;
        if (gr < M) v = *(const float4*)&in[(size_t)gr * 128 + k4];
        uint4 u; u.x = tf32r(v.x); u.y = tf32r(v.y); u.z = tf32r(v.z); u.w = tf32r(v.w);
        *(uint4*)&As[row * AST + k4] = u;
    }
}
__device__ __forceinline__ void load_W(const float* __restrict__ W, float* Ws, int t) {
    for (int idx = t; idx < 4096; idx += 256) {
        int k = idx >> 5, n4 = (idx & 31) * 4;
        float4 w = ((const float4*)W)[idx];
        uint4 u; u.x = tf32r(w.x); u.y = tf32r(w.y); u.z = tf32r(w.z); u.w = tf32r(w.w);
        *(uint4*)&Ws[k * WST + n4] = u;
    }
}

__device__ __forceinline__ void warp_mma(const float* As, const float* Ws,
                                         int wm, int wn, int g, int tg,
                                         float (&acc)[2][4][4]) {
#pragma unroll
    for (int mi = 0; mi < 2; mi++)
#pragma unroll
        for (int ni = 0; ni < 4; ni++)
#pragma unroll
            for (int c = 0; c < 4; c++) acc[mi][ni][c] = 0.f;
    const uint32_t* Au = (const uint32_t*)As;
    const uint32_t* Wu = (const uint32_t*)Ws;
#pragma unroll 4
    for (int k0 = 0; k0 < 128; k0 += 8) {
        uint32_t a[2][4];
#pragma unroll
        for (int mi = 0; mi < 2; mi++) {
            int r = wm * 32 + mi * 16 + g;
            a[mi][0] = Au[r * AST + k0 + tg];
            a[mi][1] = Au[(r + 8) * AST + k0 + tg];
            a[mi][2] = Au[r * AST + k0 + tg + 4];
            a[mi][3] = Au[(r + 8) * AST + k0 + tg + 4];
        }
#pragma unroll
        for (int ni = 0; ni < 4; ni++) {
            int cb = wn * 32 + ni * 8 + g;
            uint32_t b0 = Wu[(k0 + tg) * WST + cb];
            uint32_t b1 = Wu[(k0 + tg + 4) * WST + cb];
            mma8(acc[0][ni], a[0], b0, b1);
            mma8(acc[1][ni], a[1], b0, b1);
        }
    }
}

// EPI: 0 = float out + bias (+RELU), 1 = bf16 out raw, 2 = h-update (outp == hio)
template <int EPI, bool RELU>
__device__ __forceinline__ void run_pass(const float* __restrict__ in,
                                         float* __restrict__ outp,
                                         __nv_bfloat16* __restrict__ outb,
                                         const float* bs, float* As, const float* Ws,
                                         int M, int nt, int t) {
    int wid = t >> 5, lane = t & 31;
    int g = lane >> 2, tg = lane & 3;
    int wm = wid & 1, wn = wid >> 1;
    int tile = blockIdx.x;
    if (tile < nt) load_A(in, As, tile * 64, M, t);
    __syncthreads();
    for (; tile < nt; tile += gridDim.x) {
        float acc[2][4][4];
        warp_mma(As, Ws, wm, wn, g, tg, acc);
        __syncthreads();
        int next = tile + gridDim.x;
        if (next < nt) load_A(in, As, next * 64, M, t);  // overlaps epilogue
        int r0 = tile * 64;
#pragma unroll
        for (int mi = 0; mi < 2; mi++) {
            int row = r0 + wm * 32 + mi * 16 + g;
#pragma unroll
            for (int ni = 0; ni < 4; ni++) {
                int col = wn * 32 + ni * 8 + 2 * tg;
#pragma unroll
                for (int half = 0; half < 2; half++) {
                    int rr = row + half * 8;
                    if (rr >= M) continue;
                    float vx = acc[mi][ni][half * 2 + 0];
                    float vy = acc[mi][ni][half * 2 + 1];
                    if (EPI == 0) {
                        vx += bs[col]; vy += bs[col + 1];
                        if (RELU) { vx = fmaxf(vx, 0.f); vy = fmaxf(vy, 0.f); }
                        float2 v; v.x = vx; v.y = vy;
                        *(float2*)&outp[(size_t)rr * 128 + col] = v;
                    } else if (EPI == 1) {
                        __nv_bfloat162 v = __floats2bfloat162_rn(vx, vy);
                        *(__nv_bfloat162*)&outb[(size_t)rr * 128 + col] = v;
                    } else {
                        float mask = (g_cnt[rr] > 0) ? 1.f : 0.f;
                        float2 hv = *(const float2*)&outp[(size_t)rr * 128 + col];
                        hv.x += fmaxf(vx + bs[col]     * mask, 0.f);
                        hv.y += fmaxf(vy + bs[col + 1] * mask, 0.f);
                        *(float2*)&outp[(size_t)rr * 128 + col] = hv;
                    }
                }
            }
        }
        __syncthreads();
    }
}

template <bool RELU>
__global__ void __launch_bounds__(256, 2)
k_gemm_t(const float* __restrict__ in, const float* __restrict__ W,
         const float* __restrict__ bias, float* __restrict__ out, int M, int nt) {
    extern __shared__ float sm[];
    float* As = sm; float* Ws = sm + 64 * AST;
    __shared__ float bs[128];
    int t = threadIdx.x;
    load_W(W, Ws, t);
    if (t < 128) bs[t] = bias[t];
    run_pass<0, RELU>(in, out, nullptr, bs, As, Ws, M, nt, t);
}

__global__ void __launch_bounds__(256, 2)
k_gemmAB_t(const float* __restrict__ in, const float* __restrict__ W1a,
           const float* __restrict__ b1, const float* __restrict__ W1b,
           float* __restrict__ Aout, __nv_bfloat16* __restrict__ Bout, int M, int nt) {
    extern __shared__ float sm[];
    float* As = sm; float* Ws = sm + 64 * AST;
    __shared__ float bs[128];
    int t = threadIdx.x;
    load_W(W1a, Ws, t);
    if (t < 128) bs[t] = b1[t];
    run_pass<0, false>(in, Aout, nullptr, bs, As, Ws, M, nt, t);
    __syncthreads();
    load_W(W1b, Ws, t);
    run_pass<1, false>(in, nullptr, Bout, bs, As, Ws, M, nt, t);
}

__global__ void __launch_bounds__(256, 2)
k_fused_t(const float* __restrict__ Sin, const float* __restrict__ W2,
          const float* __restrict__ b2, float* __restrict__ hio,
          const float* __restrict__ W1a, const float* __restrict__ b1,
          const float* __restrict__ W1b,
          float* __restrict__ Aout, __nv_bfloat16* __restrict__ Bout,
          int M, int nt, int doAB) {
    extern __shared__ float sm[];
    float* As = sm; float* Ws = sm + 64 * AST;
    __shared__ float bs0[128], bs1[128];
    int t = threadIdx.x;
    load_W(W2, Ws, t);
    if (t < 128) bs0[t] = b2[t];
    if (t >= 128) bs1[t - 128] = b1[t - 128];
    run_pass<2, false>(Sin, hio, nullptr, bs0, As, Ws, M, nt, t);
    if (!doAB) return;
    __syncthreads();
    load_W(W1a, Ws, t);
    run_pass<0, false>(hio, Aout, nullptr, bs1, As, Ws, M, nt, t);
    __syncthreads();
    load_W(W1b, Ws, t);
    run_pass<1, false>(hio, nullptr, Bout, bs1, As, Ws, M, nt, t);
}

// ---------------- gather (bf16 B) ----------------
__global__ void __launch_bounds__(256)
k_gather(const float* __restrict__ w1c, int N) {
    int warp = threadIdx.x >> 5, lane = threadIdx.x & 31;
    int n = blockIdx.x * 8 + warp;
    if (n >= N) return;
    float4 wc = ((const float4*)w1c)[lane];
    float4 a = *(const float4*)&g_A[(size_t)n * 128 + lane * 4];
    int e = g_rowptr[n], e1 = g_rowptr[n + 1];
    float4 acc = make_float4(0.f, 0.f, 0.f, 0.f);
    for (; e + 4 <= e1; e += 4) {
        int s0 = g_src[e], s1 = g_src[e+1], s2 = g_src[e+2], s3 = g_src[e+3];
        float ea0 = g_eas[e], ea1 = g_eas[e+1], ea2 = g_eas[e+2], ea3 = g_eas[e+3];
        float4 b0 = ldB(g_Bm, s0, lane);
        float4 b1 = ldB(g_Bm, s1, lane);
        float4 b2 = ldB(g_Bm, s2, lane);
        float4 b3 = ldB(g_Bm, s3, lane);
        acc.x += fmaxf(a.x + b0.x + ea0 * wc.x, 0.f) + fmaxf(a.x + b1.x + ea1 * wc.x, 0.f)
               + fmaxf(a.x + b2.x + ea2 * wc.x, 0.f) + fmaxf(a.x + b3.x + ea3 * wc.x, 0.f);
        acc.y += fmaxf(a.y + b0.y + ea0 * wc.y, 0.f) + fmaxf(a.y + b1.y + ea1 * wc.y, 0.f)
               + fmaxf(a.y + b2.y + ea2 * wc.y, 0.f) + fmaxf(a.y + b3.y + ea3 * wc.y, 0.f);
        acc.z += fmaxf(a.z + b0.z + ea0 * wc.z, 0.f) + fmaxf(a.z + b1.z + ea1 * wc.z, 0.f)
               + fmaxf(a.z + b2.z + ea2 * wc.z, 0.f) + fmaxf(a.z + b3.z + ea3 * wc.z, 0.f);
        acc.w += fmaxf(a.w + b0.w + ea0 * wc.w, 0.f) + fmaxf(a.w + b1.w + ea1 * wc.w, 0.f)
               + fmaxf(a.w + b2.w + ea2 * wc.w, 0.f) + fmaxf(a.w + b3.w + ea3 * wc.w, 0.f);
    }
    for (; e < e1; e++) {
        int s0 = g_src[e];
        float ea0 = g_eas[e];
        float4 b0 = ldB(g_Bm, s0, lane);
        acc.x += fmaxf(a.x + b0.x + ea0 * wc.x, 0.f);
        acc.y += fmaxf(a.y + b0.y + ea0 * wc.y, 0.f);
        acc.z += fmaxf(a.z + b0.z + ea0 * wc.z, 0.f);
        acc.w += fmaxf(a.w + b0.w + ea0 * wc.w, 0.f);
    }
    float iv = g_inv[n];
    acc.x *= iv; acc.y *= iv; acc.z *= iv; acc.w *= iv;
    *(float4*)&g_S[(size_t)n * 128 + lane * 4] = acc;
}

// ---------------- sort / small kernels ----------------
__global__ void k_zero(int N) {
    int i = blockIdx.x * blockDim.x + threadIdx.x;
    if (i < N) g_cnt[i] = 0;
}
__global__ void k_hist(const int* __restrict__ ei, int E) {
    int i = blockIdx.x * blockDim.x + threadIdx.x;
    if (i < E) atomicAdd(&g_cnt[ei[(size_t)E + i]], 1);
}
__global__ void k_scan(int n) {
    __shared__ int wsum[32];
    __shared__ int carry;
    int t = threadIdx.x, lane = t & 31, w = t >> 5;
    if (t == 0) carry = 0;
    __syncthreads();
    for (int base = 0; base < n; base += 1024) {
        int i = base + t;
        int v = (i < n) ? g_cnt[i] : 0;
        int x = v;
#pragma unroll
        for (int o = 1; o < 32; o <<= 1) { int y = __shfl_up_sync(~0u, x, o); if (lane >= o) x += y; }
        if (lane == 31) wsum[w] = x;
        __syncthreads();
        if (w == 0) {
            int s = wsum[lane];
#pragma unroll
            for (int o = 1; o < 32; o <<= 1) { int y = __shfl_up_sync(~0u, s, o); if (lane >= o) s += y; }
            wsum[lane] = s;
        }
        __syncthreads();
        int off = carry + (w ? wsum[w - 1] : 0);
        if (i < n) g_rowptr[i] = off + x - v;
        int total = wsum[31];
        __syncthreads();
        if (t == 0) carry += total;
        __syncthreads();
    }
    if (threadIdx.x == 0) g_rowptr[n] = carry;
}
__global__ void k_prep(int N) {
    int i = blockIdx.x * blockDim.x + threadIdx.x;
    if (i < N) {
        int c = g_cnt[i];
        g_inv[i] = 1.0f / (float)(c > 1 ? c : 1);
        g_wptr[i] = g_rowptr[i];
    }
}
__global__ void k_scatter(const int* __restrict__ ei, const float* __restrict__ ea, int E) {
    int i = blockIdx.x * blockDim.x + threadIdx.x;
    if (i < E) {
        int d = ei[(size_t)E + i];
        int pos = atomicAdd(&g_wptr[d], 1);
        g_src[pos] = ei[i];
        g_eas[pos] = ea[i];
    }
}
__global__ void k_input1(const float* __restrict__ x, const float* __restrict__ w1,
                         const float* __restrict__ b1, int N) {
    int idx = blockIdx.x * blockDim.x + threadIdx.x;
    if (idx >= N * 128) return;
    int n = idx >> 7, c = idx & 127;
    float v = fmaf(x[n*3], w1[c], fmaf(x[n*3+1], w1[128+c], fmaf(x[n*3+2], w1[256+c], b1[c])));
    g_hid[idx] = fmaxf(v, 0.f);
}
__global__ void k_addfeat(const int* __restrict__ batch, int N) {
    int idx = blockIdx.x * blockDim.x + threadIdx.x;
    if (idx >= N * 128) return;
    int n = idx >> 7, c = idx & 127;
    int b = batch[n];
    g_h[idx] += g_tf[b * 128 + c] + g_cf[b * 128 + c];
}
__global__ void k_small(const float* __restrict__ tv, const float* __restrict__ cond,
                        const float* __restrict__ tw1, const float* __restrict__ tb1,
                        const float* __restrict__ tw2, const float* __restrict__ tb2,
                        const float* __restrict__ cw1, const float* __restrict__ cb1,
                        const float* __restrict__ cw2, const float* __restrict__ cb2,
                        int B, int C) {
    __shared__ float ht[Bb][Hd];
    __shared__ float hc[Bb][Hd];
    int c = threadIdx.x;
    for (int i = 0; i < B; i++) {
        ht[i][c] = fmaxf(fmaf(tv[i], tw1[c], tb1[c]), 0.f);
        float s = cb1[c];
        for (int j = 0; j < C; j++) s = fmaf(cond[i * C + j], cw1[j * 128 + c], s);
        hc[i][c] = fmaxf(s, 0.f);
    }
    __syncthreads();
    for (int i = 0; i < B; i++) {
        float s1 = tb2[c], s2 = cb2[c];
        for (int k = 0; k < 128; k++) {
            s1 = fmaf(ht[i][k], tw2[k * 128 + c], s1);
            s2 = fmaf(hc[i][k], cw2[k * 128 + c], s2);
        }
        g_tf[i * 128 + c] = s1;
        g_cf[i * 128 + c] = s2;
    }
}
__global__ void k_out2(const float* __restrict__ w2, const float* __restrict__ b2,
                       float* __restrict__ out, int N) {
    int idx = blockIdx.x * blockDim.x + threadIdx.x;
    if (idx >= N * 3) return;
    int n = idx / 3, j = idx % 3;
    float s = b2[j];
    const float* hrow = &g_hid[(size_t)n * 128];
#pragma unroll 8
    for (int k = 0; k < 128; k++) s = fmaf(hrow[k], w2[k * 3 + j], s);
    out[idx] = s;
}

extern "C" void kernel_launch(void* const* d_in, const int* in_sizes, int n_in,
                              void* d_out, int out_size) {
    const float* x      = (const float*)d_in[0];
    const int*   ei     = (const int*)d_in[1];
    const float* ea     = (const float*)d_in[2];
    const float* tvec   = (const float*)d_in[3];
    const int*   batch  = (const int*)d_in[4];
    const float* cond   = (const float*)d_in[5];
    const float* in_w1  = (const float*)d_in[6];
    const float* in_b1  = (const float*)d_in[7];
    const float* in_w2  = (const float*)d_in[8];
    const float* in_b2  = (const float*)d_in[9];
    const float* t_w1   = (const float*)d_in[10];
    const float* t_b1   = (const float*)d_in[11];
    const float* t_w2   = (const float*)d_in[12];
    const float* t_b2   = (const float*)d_in[13];
    const float* c_w1   = (const float*)d_in[14];
    const float* c_b1   = (const float*)d_in[15];
    const float* c_w2   = (const float*)d_in[16];
    const float* c_b2   = (const float*)d_in[17];
    const float* convW1 = (const float*)d_in[18];
    const float* convb1 = (const float*)d_in[19];
    const float* convW2 = (const float*)d_in[20];
    const float* convb2 = (const float*)d_in[21];
    const float* out_w1 = (const float*)d_in[22];
    const float* out_b1 = (const float*)d_in[23];
    const float* out_w2 = (const float*)d_in[24];
    const float* out_b2 = (const float*)d_in[25];

    int N = in_sizes[0] / 3;
    int E = in_sizes[1] / 2;
    int B = in_sizes[3];
    int C = in_sizes[5] / (B > 0 ? B : 1);
    float* out = (float*)d_out;

    float *p_h = 0, *p_A = 0, *p_S = 0, *p_hid = 0;
    __nv_bfloat16* p_Bm = 0;
    cudaGetSymbolAddress((void**)&p_h,   g_h);
    cudaGetSymbolAddress((void**)&p_A,   g_A);
    cudaGetSymbolAddress((void**)&p_Bm,  g_Bm);
    cudaGetSymbolAddress((void**)&p_S,   g_S);
    cudaGetSymbolAddress((void**)&p_hid, g_hid);

    cudaFuncSetAttribute(k_gemm_t<false>, cudaFuncAttributeMaxDynamicSharedMemorySize, SMEMX);
    cudaFuncSetAttribute(k_gemm_t<true>,  cudaFuncAttributeMaxDynamicSharedMemorySize, SMEMX);
    cudaFuncSetAttribute(k_gemmAB_t,      cudaFuncAttributeMaxDynamicSharedMemorySize, SMEMX);
    cudaFuncSetAttribute(k_fused_t,       cudaFuncAttributeMaxDynamicSharedMemorySize, SMEMX);

    int nt = (N + 63) / 64;

    k_input1<<<(N * 128 + 255) / 256, 256>>>(x, in_w1, in_b1, N);
    k_small<<<1, 128>>>(tvec, cond, t_w1, t_b1, t_w2, t_b2, c_w1, c_b1, c_w2, c_b2, B, C);
    k_zero<<<(N + 255) / 256, 256>>>(N);
    k_gemm_t<false><<<PGRID, 256, SMEMX>>>(p_hid, in_w2, in_b2, p_h, N, nt);   // ncu slot 4
    k_hist<<<(E + 255) / 256, 256>>>(ei, E);
    k_scan<<<1, 1024>>>(N);
    k_prep<<<(N + 255) / 256, 256>>>(N);
    k_scatter<<<(E + 255) / 256, 256>>>(ei, ea, E);
    k_addfeat<<<(N * 128 + 255) / 256, 256>>>(batch, N);

    k_gemmAB_t<<<PGRID, 256, SMEMX>>>(p_h, convW1, convb1, convW1 + 128 * 128, p_A, p_Bm, N, nt);

    for (int l = 0; l < 6; l++) {
        const float* W1 = convW1 + (size_t)l * 257 * 128;
        const float* W1n = convW1 + (size_t)(l + 1) * 257 * 128;
        k_gather<<<(N + 7) / 8, 256>>>(W1 + 256 * 128, N);
        int doAB = (l < 5) ? 1 : 0;
        k_fused_t<<<PGRID, 256, SMEMX>>>(p_S, convW2 + (size_t)l * 128 * 128, convb2 + l * 128,
                                         p_h,
                                         doAB ? W1n : convW1,
                                         doAB ? (convb1 + (l + 1) * 128) : convb1,
                                         doAB ? (W1n + 128 * 128) : convW1,
                                         p_A, p_Bm, N, nt, doAB);
    }

    k_gemm_t<true><<<PGRID, 256, SMEMX>>>(p_h, out_w1, out_b1, p_hid, N, nt);
    k_out2<<<(N * 3 + 255) / 256, 256>>>(out_w2, out_b2, out, N);
}

// round 17
// speedup vs baseline: 1.6653x; 1.0463x over previous
#include <cuda_runtime.h>
#include <cuda_bf16.h>
#include <cstdint>

#define Nn 100000
#define Ee 1600000
#define Hd 128
#define Bb 4
#define AST 132
#define WST 136
#define SMEMX ((64 * AST + 128 * WST) * 4)
#define PGRID 296
#define NBLK ((Nn + 255) / 256)

__device__ __align__(256) int   g_cnt[Nn];
__device__ __align__(256) int   g_rowptr[Nn + 1];
__device__ __align__(256) int   g_wptr[Nn];
__device__ __align__(256) int   g_bsum[NBLK];
__device__ __align__(256) int   g_boff[NBLK];
__device__ __align__(256) int   g_src[Ee];
__device__ __align__(256) float g_eas[Ee];
__device__ __align__(256) float g_inv[Nn];
__device__ __align__(256) float g_h[(size_t)Nn * Hd];
__device__ __align__(256) float g_A[(size_t)Nn * Hd];
__device__ __align__(256) __nv_bfloat16 g_Bm[(size_t)Nn * Hd];
__device__ __align__(256) float g_S[(size_t)Nn * Hd];
__device__ __align__(256) float g_hid[(size_t)Nn * Hd];
__device__ __align__(256) float g_tf[Bb * Hd];
__device__ __align__(256) float g_cf[Bb * Hd];

__device__ __forceinline__ uint32_t tf32r(float x) {
    uint32_t r;
    asm("cvt.rna.tf32.f32 %0, %1;" : "=r"(r) : "f"(x));
    return r;
}
__device__ __forceinline__ void mma8(float* d, const uint32_t* a, uint32_t b0, uint32_t b1) {
    asm volatile(
        "mma.sync.aligned.m16n8k8.row.col.f32.tf32.tf32.f32 "
        "{%0,%1,%2,%3}, {%4,%5,%6,%7}, {%8,%9}, {%0,%1,%2,%3};"
        : "+f"(d[0]), "+f"(d[1]), "+f"(d[2]), "+f"(d[3])
        : "r"(a[0]), "r"(a[1]), "r"(a[2]), "r"(a[3]), "r"(b0), "r"(b1));
}

__device__ __forceinline__ float4 ldB(const __nv_bfloat16* __restrict__ Bm, int s, int lane) {
    uint2 p = *(const uint2*)(Bm + (size_t)s * 128 + lane * 4);
    __nv_bfloat162 u0 = *reinterpret_cast<__nv_bfloat162*>(&p.x);
    __nv_bfloat162 u1 = *reinterpret_cast<__nv_bfloat162*>(&p.y);
    float2 f0 = __bfloat1622float2(u0);
    float2 f1 = __bfloat1622float2(u1);
    return make_float4(f0.x, f0.y, f1.x, f1.y);
}

__device__ __forceinline__ void load_A(const float* __restrict__ in, float* As,
                                       int r0, int M, int t) {
    for (int idx = t; idx < 2048; idx += 256) {
        int row = idx >> 5, k4 = (idx & 31) * 4;
        float4 v = make_float4(0.f, 0.f, 0.f, 0.f);
        int gr = r0 + row;
        if (gr < M) v = *(const float4*)&in[(size_t)gr * 128 + k4];
        uint4 u; u.x = tf32r(v.x); u.y = tf32r(v.y); u.z = tf32r(v.z); u.w = tf32r(v.w);
        *(uint4*)&As[row * AST + k4] = u;
    }
}
__device__ __forceinline__ void load_W(const float* __restrict__ W, float* Ws, int t) {
    for (int idx = t; idx < 4096; idx += 256) {
        int k = idx >> 5, n4 = (idx & 31) * 4;
        float4 w = ((const float4*)W)[idx];
        uint4 u; u.x = tf32r(w.x); u.y = tf32r(w.y); u.z = tf32r(w.z); u.w = tf32r(w.w);
        *(uint4*)&Ws[k * WST + n4] = u;
    }
}

__device__ __forceinline__ void warp_mma(const float* As, const float* Ws,
                                         int wm, int wn, int g, int tg,
                                         float (&acc)[2][4][4]) {
#pragma unroll
    for (int mi = 0; mi < 2; mi++)
#pragma unroll
        for (int ni = 0; ni < 4; ni++)
#pragma unroll
            for (int c = 0; c < 4; c++) acc[mi][ni][c] = 0.f;
    const uint32_t* Au = (const uint32_t*)As;
    const uint32_t* Wu = (const uint32_t*)Ws;
#pragma unroll 4
    for (int k0 = 0; k0 < 128; k0 += 8) {
        uint32_t a[2][4];
#pragma unroll
        for (int mi = 0; mi < 2; mi++) {
            int r = wm * 32 + mi * 16 + g;
            a[mi][0] = Au[r * AST + k0 + tg];
            a[mi][1] = Au[(r + 8) * AST + k0 + tg];
            a[mi][2] = Au[r * AST + k0 + tg + 4];
            a[mi][3] = Au[(r + 8) * AST + k0 + tg + 4];
        }
#pragma unroll
        for (int ni = 0; ni < 4; ni++) {
            int cb = wn * 32 + ni * 8 + g;
            uint32_t b0 = Wu[(k0 + tg) * WST + cb];
            uint32_t b1 = Wu[(k0 + tg + 4) * WST + cb];
            mma8(acc[0][ni], a[0], b0, b1);
            mma8(acc[1][ni], a[1], b0, b1);
        }
    }
}

// EPI: 0 = float out + bias (+RELU), 1 = bf16 out raw, 2 = h-update (outp == hio)
template <int EPI, bool RELU>
__device__ __forceinline__ void run_pass(const float* __restrict__ in,
                                         float* __restrict__ outp,
                                         __nv_bfloat16* __restrict__ outb,
                                         const float* bs, float* As, const float* Ws,
                                         int M, int nt, int t) {
    int wid = t >> 5, lane = t & 31;
    int g = lane >> 2, tg = lane & 3;
    int wm = wid & 1, wn = wid >> 1;
    int tile = blockIdx.x;
    if (tile < nt) load_A(in, As, tile * 64, M, t);
    __syncthreads();
    for (; tile < nt; tile += gridDim.x) {
        float acc[2][4][4];
        warp_mma(As, Ws, wm, wn, g, tg, acc);
        __syncthreads();
        int next = tile + gridDim.x;
        if (next < nt) load_A(in, As, next * 64, M, t);
        int r0 = tile * 64;
#pragma unroll
        for (int mi = 0; mi < 2; mi++) {
            int row = r0 + wm * 32 + mi * 16 + g;
#pragma unroll
            for (int ni = 0; ni < 4; ni++) {
                int col = wn * 32 + ni * 8 + 2 * tg;
#pragma unroll
                for (int half = 0; half < 2; half++) {
                    int rr = row + half * 8;
                    if (rr >= M) continue;
                    float vx = acc[mi][ni][half * 2 + 0];
                    float vy = acc[mi][ni][half * 2 + 1];
                    if (EPI == 0) {
                        vx += bs[col]; vy += bs[col + 1];
                        if (RELU) { vx = fmaxf(vx, 0.f); vy = fmaxf(vy, 0.f); }
                        float2 v; v.x = vx; v.y = vy;
                        *(float2*)&outp[(size_t)rr * 128 + col] = v;
                    } else if (EPI == 1) {
                        __nv_bfloat162 v = __floats2bfloat162_rn(vx, vy);
                        *(__nv_bfloat162*)&outb[(size_t)rr * 128 + col] = v;
                    } else {
                        float mask = (g_cnt[rr] > 0) ? 1.f : 0.f;
                        float2 hv = *(const float2*)&outp[(size_t)rr * 128 + col];
                        hv.x += fmaxf(vx + bs[col]     * mask, 0.f);
                        hv.y += fmaxf(vy + bs[col + 1] * mask, 0.f);
                        *(float2*)&outp[(size_t)rr * 128 + col] = hv;
                    }
                }
            }
        }
        __syncthreads();
    }
}

template <bool RELU>
__global__ void __launch_bounds__(256, 2)
k_gemm_t(const float* __restrict__ in, const float* __restrict__ W,
         const float* __restrict__ bias, float* __restrict__ out, int M, int nt) {
    extern __shared__ float sm[];
    float* As = sm; float* Ws = sm + 64 * AST;
    __shared__ float bs[128];
    int t = threadIdx.x;
    load_W(W, Ws, t);
    if (t < 128) bs[t] = bias[t];
    run_pass<0, RELU>(in, out, nullptr, bs, As, Ws, M, nt, t);
}

__global__ void __launch_bounds__(256, 2)
k_gemmAB_t(const float* __restrict__ in, const float* __restrict__ W1a,
           const float* __restrict__ b1, const float* __restrict__ W1b,
           float* __restrict__ Aout, __nv_bfloat16* __restrict__ Bout, int M, int nt) {
    extern __shared__ float sm[];
    float* As = sm; float* Ws = sm + 64 * AST;
    __shared__ float bs[128];
    int t = threadIdx.x;
    load_W(W1a, Ws, t);
    if (t < 128) bs[t] = b1[t];
    run_pass<0, false>(in, Aout, nullptr, bs, As, Ws, M, nt, t);
    __syncthreads();
    load_W(W1b, Ws, t);
    run_pass<1, false>(in, nullptr, Bout, bs, As, Ws, M, nt, t);
}

__global__ void __launch_bounds__(256, 2)
k_fused_t(const float* __restrict__ Sin, const float* __restrict__ W2,
          const float* __restrict__ b2, float* __restrict__ hio,
          const float* __restrict__ W1a, const float* __restrict__ b1,
          const float* __restrict__ W1b,
          float* __restrict__ Aout, __nv_bfloat16* __restrict__ Bout,
          int M, int nt, int doAB) {
    extern __shared__ float sm[];
    float* As = sm; float* Ws = sm + 64 * AST;
    __shared__ float bs0[128], bs1[128];
    int t = threadIdx.x;
    load_W(W2, Ws, t);
    if (t < 128) bs0[t] = b2[t];
    if (t >= 128) bs1[t - 128] = b1[t - 128];
    run_pass<2, false>(Sin, hio, nullptr, bs0, As, Ws, M, nt, t);
    if (!doAB) return;
    __syncthreads();
    load_W(W1a, Ws, t);
    run_pass<0, false>(hio, Aout, nullptr, bs1, As, Ws, M, nt, t);
    __syncthreads();
    load_W(W1b, Ws, t);
    run_pass<1, false>(hio, nullptr, Bout, bs1, As, Ws, M, nt, t);
}

// ---------------- gather (bf16 B, 8-deep unroll for MLP) ----------------
__global__ void __launch_bounds__(256)
k_gather(const float* __restrict__ w1c, int N) {
    int warp = threadIdx.x >> 5, lane = threadIdx.x & 31;
    int n = blockIdx.x * 8 + warp;
    if (n >= N) return;
    float4 wc = ((const float4*)w1c)[lane];
    float4 a = *(const float4*)&g_A[(size_t)n * 128 + lane * 4];
    int e = g_rowptr[n], e1 = g_rowptr[n + 1];
    float4 acc = make_float4(0.f, 0.f, 0.f, 0.f);
    for (; e + 8 <= e1; e += 8) {
        int   si[8];
        float ei[8];
        float4 bv[8];
#pragma unroll
        for (int j = 0; j < 8; j++) { si[j] = g_src[e + j]; ei[j] = g_eas[e + j]; }
#pragma unroll
        for (int j = 0; j < 8; j++) bv[j] = ldB(g_Bm, si[j], lane);
#pragma unroll
        for (int j = 0; j < 8; j++) {
            acc.x += fmaxf(a.x + bv[j].x + ei[j] * wc.x, 0.f);
            acc.y += fmaxf(a.y + bv[j].y + ei[j] * wc.y, 0.f);
            acc.z += fmaxf(a.z + bv[j].z + ei[j] * wc.z, 0.f);
            acc.w += fmaxf(a.w + bv[j].w + ei[j] * wc.w, 0.f);
        }
    }
    for (; e < e1; e++) {
        int s0 = g_src[e];
        float ea0 = g_eas[e];
        float4 b0 = ldB(g_Bm, s0, lane);
        acc.x += fmaxf(a.x + b0.x + ea0 * wc.x, 0.f);
        acc.y += fmaxf(a.y + b0.y + ea0 * wc.y, 0.f);
        acc.z += fmaxf(a.z + b0.z + ea0 * wc.z, 0.f);
        acc.w += fmaxf(a.w + b0.w + ea0 * wc.w, 0.f);
    }
    float iv = g_inv[n];
    acc.x *= iv; acc.y *= iv; acc.z *= iv; acc.w *= iv;
    *(float4*)&g_S[(size_t)n * 128 + lane * 4] = acc;
}

// ---------------- parallel 3-phase scan ----------------
__global__ void k_zero(int N) {
    int i = blockIdx.x * blockDim.x + threadIdx.x;
    if (i < N) g_cnt[i] = 0;
}
__global__ void k_hist(const int* __restrict__ ei, int E) {
    int i = blockIdx.x * blockDim.x + threadIdx.x;
    if (i < E) atomicAdd(&g_cnt[ei[(size_t)E + i]], 1);
}
// phase 1: per-block exclusive scan of g_cnt -> g_rowptr (partial), block sums -> g_bsum
__global__ void __launch_bounds__(256)
k_bscan(int N) {
    __shared__ int ws[8];
    int b = blockIdx.x, t = threadIdx.x, i = b * 256 + t;
    int lane = t & 31, w = t >> 5;
    int v = (i < N) ? g_cnt[i] : 0;
    int x = v;
#pragma unroll
    for (int o = 1; o < 32; o <<= 1) { int y = __shfl_up_sync(~0u, x, o); if (lane >= o) x += y; }
    if (lane == 31) ws[w] = x;
    __syncthreads();
    if (t == 0) {
        int run = 0;
#pragma unroll
        for (int j = 0; j < 8; j++) { int tmp = ws[j]; ws[j] = run; run += tmp; }
        g_bsum[b] = run;
    }
    __syncthreads();
    if (i < N) g_rowptr[i] = x - v + ws[w];
}
// phase 2: single block scans the NBLK block sums (exclusive) -> g_boff
__global__ void __launch_bounds__(512)
k_sscan(int nb) {
    __shared__ int ws[16];
    int t = threadIdx.x, lane = t & 31, w = t >> 5;
    int v = (t < nb) ? g_bsum[t] : 0;
    int x = v;
#pragma unroll
    for (int o = 1; o < 32; o <<= 1) { int y = __shfl_up_sync(~0u, x, o); if (lane >= o) x += y; }
    if (lane == 31) ws[w] = x;
    __syncthreads();
    if (t == 0) {
        int run = 0;
#pragma unroll
        for (int j = 0; j < 16; j++) { int tmp = ws[j]; ws[j] = run; run += tmp; }
    }
    __syncthreads();
    if (t < nb) g_boff[t] = x - v + ws[w];
}
// phase 3: add block offsets; produce final rowptr, wptr, inv; rowptr[N]=E
__global__ void k_finish(int N, int E) {
    int i = blockIdx.x * blockDim.x + threadIdx.x;
    if (i < N) {
        int r = g_rowptr[i] + g_boff[i >> 8];
        g_rowptr[i] = r;
        g_wptr[i] = r;
        int c = g_cnt[i];
        g_inv[i] = 1.0f / (float)(c > 1 ? c : 1);
    }
    if (i == 0) g_rowptr[N] = E;
}
__global__ void k_scatter(const int* __restrict__ ei, const float* __restrict__ ea, int E) {
    int i = blockIdx.x * blockDim.x + threadIdx.x;
    if (i < E) {
        int d = ei[(size_t)E + i];
        int pos = atomicAdd(&g_wptr[d], 1);
        g_src[pos] = ei[i];
        g_eas[pos] = ea[i];
    }
}
__global__ void k_input1(const float* __restrict__ x, const float* __restrict__ w1,
                         const float* __restrict__ b1, int N) {
    int idx = blockIdx.x * blockDim.x + threadIdx.x;
    if (idx >= N * 128) return;
    int n = idx >> 7, c = idx & 127;
    float v = fmaf(x[n*3], w1[c], fmaf(x[n*3+1], w1[128+c], fmaf(x[n*3+2], w1[256+c], b1[c])));
    g_hid[idx] = fmaxf(v, 0.f);
}
__global__ void k_addfeat(const int* __restrict__ batch, int N) {
    int idx = blockIdx.x * blockDim.x + threadIdx.x;
    if (idx >= N * 128) return;
    int n = idx >> 7, c = idx & 127;
    int b = batch[n];
    g_h[idx] += g_tf[b * 128 + c] + g_cf[b * 128 + c];
}
__global__ void k_small(const float* __restrict__ tv, const float* __restrict__ cond,
                        const float* __restrict__ tw1, const float* __restrict__ tb1,
                        const float* __restrict__ tw2, const float* __restrict__ tb2,
                        const float* __restrict__ cw1, const float* __restrict__ cb1,
                        const float* __restrict__ cw2, const float* __restrict__ cb2,
                        int B, int C) {
    __shared__ float ht[Bb][Hd];
    __shared__ float hc[Bb][Hd];
    int c = threadIdx.x;
    for (int i = 0; i < B; i++) {
        ht[i][c] = fmaxf(fmaf(tv[i], tw1[c], tb1[c]), 0.f);
        float s = cb1[c];
        for (int j = 0; j < C; j++) s = fmaf(cond[i * C + j], cw1[j * 128 + c], s);
        hc[i][c] = fmaxf(s, 0.f);
    }
    __syncthreads();
    for (int i = 0; i < B; i++) {
        float s1 = tb2[c], s2 = cb2[c];
        for (int k = 0; k < 128; k++) {
            s1 = fmaf(ht[i][k], tw2[k * 128 + c], s1);
            s2 = fmaf(hc[i][k], cw2[k * 128 + c], s2);
        }
        g_tf[i * 128 + c] = s1;
        g_cf[i * 128 + c] = s2;
    }
}
__global__ void k_out2(const float* __restrict__ w2, const float* __restrict__ b2,
                       float* __restrict__ out, int N) {
    int idx = blockIdx.x * blockDim.x + threadIdx.x;
    if (idx >= N * 3) return;
    int n = idx / 3, j = idx % 3;
    float s = b2[j];
    const float* hrow = &g_hid[(size_t)n * 128];
#pragma unroll 8
    for (int k = 0; k < 128; k++) s = fmaf(hrow[k], w2[k * 3 + j], s);
    out[idx] = s;
}

extern "C" void kernel_launch(void* const* d_in, const int* in_sizes, int n_in,
                              void* d_out, int out_size) {
    const float* x      = (const float*)d_in[0];
    const int*   ei     = (const int*)d_in[1];
    const float* ea     = (const float*)d_in[2];
    const float* tvec   = (const float*)d_in[3];
    const int*   batch  = (const int*)d_in[4];
    const float* cond   = (const float*)d_in[5];
    const float* in_w1  = (const float*)d_in[6];
    const float* in_b1  = (const float*)d_in[7];
    const float* in_w2  = (const float*)d_in[8];
    const float* in_b2  = (const float*)d_in[9];
    const float* t_w1   = (const float*)d_in[10];
    const float* t_b1   = (const float*)d_in[11];
    const float* t_w2   = (const float*)d_in[12];
    const float* t_b2   = (const float*)d_in[13];
    const float* c_w1   = (const float*)d_in[14];
    const float* c_b1   = (const float*)d_in[15];
    const float* c_w2   = (const float*)d_in[16];
    const float* c_b2   = (const float*)d_in[17];
    const float* convW1 = (const float*)d_in[18];
    const float* convb1 = (const float*)d_in[19];
    const float* convW2 = (const float*)d_in[20];
    const float* convb2 = (const float*)d_in[21];
    const float* out_w1 = (const float*)d_in[22];
    const float* out_b1 = (const float*)d_in[23];
    const float* out_w2 = (const float*)d_in[24];
    const float* out_b2 = (const float*)d_in[25];

    int N = in_sizes[0] / 3;
    int E = in_sizes[1] / 2;
    int B = in_sizes[3];
    int C = in_sizes[5] / (B > 0 ? B : 1);
    float* out = (float*)d_out;

    float *p_h = 0, *p_A = 0, *p_S = 0, *p_hid = 0;
    __nv_bfloat16* p_Bm = 0;
    cudaGetSymbolAddress((void**)&p_h,   g_h);
    cudaGetSymbolAddress((void**)&p_A,   g_A);
    cudaGetSymbolAddress((void**)&p_Bm,  g_Bm);
    cudaGetSymbolAddress((void**)&p_S,   g_S);
    cudaGetSymbolAddress((void**)&p_hid, g_hid);

    cudaFuncSetAttribute(k_gemm_t<false>, cudaFuncAttributeMaxDynamicSharedMemorySize, SMEMX);
    cudaFuncSetAttribute(k_gemm_t<true>,  cudaFuncAttributeMaxDynamicSharedMemorySize, SMEMX);
    cudaFuncSetAttribute(k_gemmAB_t,      cudaFuncAttributeMaxDynamicSharedMemorySize, SMEMX);
    cudaFuncSetAttribute(k_fused_t,       cudaFuncAttributeMaxDynamicSharedMemorySize, SMEMX);

    int nt = (N + 63) / 64;
    int nb = (N + 255) / 256;

    k_input1<<<(N * 128 + 255) / 256, 256>>>(x, in_w1, in_b1, N);
    k_small<<<1, 128>>>(tvec, cond, t_w1, t_b1, t_w2, t_b2, c_w1, c_b1, c_w2, c_b2, B, C);
    k_zero<<<(N + 255) / 256, 256>>>(N);
    k_gemm_t<false><<<PGRID, 256, SMEMX>>>(p_hid, in_w2, in_b2, p_h, N, nt);   // ncu slot 4
    k_hist<<<(E + 255) / 256, 256>>>(ei, E);
    k_bscan<<<nb, 256>>>(N);
    k_sscan<<<1, 512>>>(nb);
    k_finish<<<(N + 255) / 256, 256>>>(N, E);
    k_scatter<<<(E + 255) / 256, 256>>>(ei, ea, E);
    k_addfeat<<<(N * 128 + 255) / 256, 256>>>(batch, N);

    k_gemmAB_t<<<PGRID, 256, SMEMX>>>(p_h, convW1, convb1, convW1 + 128 * 128, p_A, p_Bm, N, nt);

    for (int l = 0; l < 6; l++) {
        const float* W1 = convW1 + (size_t)l * 257 * 128;
        const float* W1n = convW1 + (size_t)(l + 1) * 257 * 128;
        k_gather<<<(N + 7) / 8, 256>>>(W1 + 256 * 128, N);
        int doAB = (l < 5) ? 1 : 0;
        k_fused_t<<<PGRID, 256, SMEMX>>>(p_S, convW2 + (size_t)l * 128 * 128, convb2 + l * 128,
                                         p_h,
                                         doAB ? W1n : convW1,
                                         doAB ? (convb1 + (l + 1) * 128) : convb1,
                                         doAB ? (W1n + 128 * 128) : convW1,
                                         p_A, p_Bm, N, nt, doAB);
    }

    k_gemm_t<true><<<PGRID, 256, SMEMX>>>(p_h, out_w1, out_b1, p_hid, N, nt);
    k_out2<<<(N * 3 + 255) / 256, 256>>>(out_w2, out_b2, out, N);
}